// round 10
// baseline (speedup 1.0000x reference)
#include <cuda_runtime.h>
#include <cuda_bf16.h>
#include <mma.h>

using namespace nvcuda;

#define NN 100000
#define NE 1600000
#define OD 64
#define ID 256

#define BM 64
#define KC 32
#define AST 40   // smem A stride (32 + 8 pad), 80B rows, 16B-aligned

// scratch: pre_sup for both supports, [2][NN][OD]
__device__ float g_pre[2 * NN * OD];
// bf16-split W: [256][128] row-major, col = sup*64 + o
__device__ __nv_bfloat16 g_Wh[ID * 128];
__device__ __nv_bfloat16 g_Wl[ID * 128];

__global__ void __launch_bounds__(256) convW_kernel(const float* __restrict__ W) {
    int idx = blockIdx.x * 256 + threadIdx.x;
    if (idx >= ID * 128) return;
    int k = idx >> 7, c = idx & 127;
    int sup = c >> 6, o = c & 63;
    float w = W[(size_t)sup * ID * OD + (size_t)k * OD + o];
    __nv_bfloat16 h = __float2bfloat16(w);
    g_Wh[idx] = h;
    g_Wl[idx] = __float2bfloat16(w - __bfloat162float(h));
}

// GEMM via bf16 tensor cores, 3-term split emulation of fp32.
// C[64 x 128] per block, 8 warps: warp grid 4(M) x 2(N), warp tile 16 x 64.
__global__ void __launch_bounds__(256) gemm_mma_kernel(const float* __restrict__ X) {
    __shared__ __nv_bfloat16 Ah[BM * AST];
    __shared__ __nv_bfloat16 Al[BM * AST];
    __shared__ __nv_bfloat16 Bh[KC * 128];
    __shared__ __nv_bfloat16 Bl[KC * 128];

    const int tid = threadIdx.x;
    const int brow = blockIdx.x * BM;
    const int wid = tid >> 5;
    const int wm = wid & 3;    // 0..3 -> m-tile of 16 rows
    const int wn = wid >> 2;   // 0..1 -> 64-col half (= support)

    wmma::fragment<wmma::accumulator, 16, 16, 16, float> c[4];
#pragma unroll
    for (int i = 0; i < 4; i++) wmma::fill_fragment(c[i], 0.f);

    for (int k0 = 0; k0 < ID; k0 += KC) {
        __syncthreads();  // protect smem from previous iteration's mma reads

        // stage X chunk [64 rows][32 k] and split to bf16 hi/lo
#pragma unroll
        for (int it = 0; it < 2; it++) {
            int idx = tid + it * 256;     // 0..511
            int r = idx >> 3;             // row 0..63
            int c4 = idx & 7;             // float4 within the 32-k chunk
            float4 v = make_float4(0.f, 0.f, 0.f, 0.f);
            if (brow + r < NN)
                v = *reinterpret_cast<const float4*>(X + (size_t)(brow + r) * ID + k0 + c4 * 4);
            __nv_bfloat16* ph = &Ah[r * AST + c4 * 4];
            __nv_bfloat16* pl = &Al[r * AST + c4 * 4];
            float xs[4] = {v.x, v.y, v.z, v.w};
#pragma unroll
            for (int j = 0; j < 4; j++) {
                __nv_bfloat16 h = __float2bfloat16(xs[j]);
                ph[j] = h;
                pl[j] = __float2bfloat16(xs[j] - __bfloat162float(h));
            }
        }

        // stage W chunk [32][128] hi+lo (contiguous 8KB each)
        {
            const uint4* sh = reinterpret_cast<const uint4*>(g_Wh + k0 * 128);
            const uint4* sl = reinterpret_cast<const uint4*>(g_Wl + k0 * 128);
            uint4* dh = reinterpret_cast<uint4*>(Bh);
            uint4* dl = reinterpret_cast<uint4*>(Bl);
            dh[tid] = sh[tid];
            dh[tid + 256] = sh[tid + 256];
            dl[tid] = sl[tid];
            dl[tid + 256] = sl[tid + 256];
        }
        __syncthreads();

#pragma unroll
        for (int kk = 0; kk < KC; kk += 16) {
            wmma::fragment<wmma::matrix_a, 16, 16, 16, __nv_bfloat16, wmma::row_major> ah, al;
            wmma::load_matrix_sync(ah, &Ah[(wm * 16) * AST + kk], AST);
            wmma::load_matrix_sync(al, &Al[(wm * 16) * AST + kk], AST);
#pragma unroll
            for (int nt = 0; nt < 4; nt++) {
                wmma::fragment<wmma::matrix_b, 16, 16, 16, __nv_bfloat16, wmma::row_major> bh, bl;
                int col = wn * 64 + nt * 16;
                wmma::load_matrix_sync(bh, &Bh[kk * 128 + col], 128);
                wmma::load_matrix_sync(bl, &Bl[kk * 128 + col], 128);
                wmma::mma_sync(c[nt], ah, bh, c[nt]);
                wmma::mma_sync(c[nt], ah, bl, c[nt]);
                wmma::mma_sync(c[nt], al, bh, c[nt]);
            }
        }
    }

    // NN % 16 == 0, row0 multiple of 16 -> row0 < NN implies the full 16-row
    // tile is in range; otherwise it is entirely out of range.
    int row0 = brow + wm * 16;
    if (row0 < NN) {
#pragma unroll
        for (int nt = 0; nt < 4; nt++) {
            float* dst = g_pre + (size_t)wn * NN * OD + (size_t)row0 * OD + nt * 16;
            wmma::store_matrix_sync(dst, c[nt], OD, wmma::mem_row_major);
        }
    }
}

// SPMM scatter: 16 threads per (support, edge); each handles one float4 of the
// 64-wide row. Gather from g_pre (L2-resident), scale by edge_val, vector RED
// (no-return atomic) into out.
__global__ void __launch_bounds__(256) spmm_kernel(const float* __restrict__ ev,
                                                   const int* __restrict__ es,
                                                   const int* __restrict__ ed,
                                                   float* __restrict__ out) {
    int idx = blockIdx.x * 256 + threadIdx.x;
    int e = idx >> 4;               // 0 .. 2*NE-1 (arrays are [2][NE] contiguous)
    if (e >= 2 * NE) return;
    int t = idx & 15;

    int src  = __ldg(es + e);
    int dst  = __ldg(ed + e);
    float val = __ldg(ev + e);
    int sup = (e >= NE) ? 1 : 0;

    const float4* prow =
        reinterpret_cast<const float4*>(g_pre + (size_t)sup * NN * OD + (size_t)src * OD);
    float4 v = __ldg(prow + t);

    float* addr = out + (size_t)dst * OD + t * 4;
    asm volatile("red.global.add.v4.f32 [%0], {%1, %2, %3, %4};"
                 :: "l"(addr), "f"(v.x * val), "f"(v.y * val), "f"(v.z * val), "f"(v.w * val)
                 : "memory");
}

__global__ void __launch_bounds__(256) relu_kernel(float4* __restrict__ out, int n4) {
    int i = blockIdx.x * 256 + threadIdx.x;
    if (i < n4) {
        float4 v = out[i];
        v.x = fmaxf(v.x, 0.f);
        v.y = fmaxf(v.y, 0.f);
        v.z = fmaxf(v.z, 0.f);
        v.w = fmaxf(v.w, 0.f);
        out[i] = v;
    }
}

extern "C" void kernel_launch(void* const* d_in, const int* in_sizes, int n_in,
                              void* d_out, int out_size) {
    const float* x  = (const float*)d_in[0];   // [NN, 256]
    const float* W  = (const float*)d_in[1];   // [2, 256, 64]
    const float* ev = (const float*)d_in[2];   // [2, NE]
    const int*   es = (const int*)d_in[3];     // [2, NE]
    const int*   ed = (const int*)d_in[4];     // [2, NE]
    float* out = (float*)d_out;                // [NN, 64]

    const int n4 = NN * OD / 4;  // 1.6M float4

    cudaMemsetAsync(d_out, 0, (size_t)NN * OD * sizeof(float));
    convW_kernel<<<(ID * 128 + 255) / 256, 256>>>(W);
    gemm_mma_kernel<<<(NN + BM - 1) / BM, 256>>>(x);

    const long long total = (long long)2 * NE * 16;
    spmm_kernel<<<(int)((total + 255) / 256), 256>>>(ev, es, ed, out);

    relu_kernel<<<(n4 + 255) / 256, 256>>>((float4*)out, n4);
}

// round 17
// speedup vs baseline: 1.0371x; 1.0371x over previous
#include <cuda_runtime.h>
#include <cuda_fp16.h>

#define NN 100000
#define NE 1600000
#define OD 64
#define ID 256

// pre_sup for both supports in fp16: [2][NN][OD]  (25.6 MB, L2-resident)
__device__ __half g_preh[2 * NN * OD];

// packed f32x2 fma: d = a*b + d  (SASS FFMA2; PTX f32x2 requires sm_100+, not 'a'-gated)
#define FMA2(d, a, b) \
    asm("fma.rn.f32x2 %0, %1, %2, %0;" : "+l"(d) : "l"(a), "l"(b))

#define SWB(x) ((x) ^ (((x) >> 3) & 0x70))

// GEMM: g_preh[s][m][o] = (half) sum_k x[m][k] * W[s][k][o]
// 128x128 tile, 256 threads, 8 rows x 8 cols per thread, BK=8.
// Inner product via packed f32x2: acc pairs along M (rows 2ip, 2ip+1),
// B staged duplicated {b,b} so no per-iteration packing movs.
__global__ void __launch_bounds__(256) gemm_f32x2_kernel(const float* __restrict__ X,
                                                         const float* __restrict__ W) {
    __shared__ __align__(1024) float2 Bs2[8][128];  // [k][n] duplicated, SW128-swizzled rows
    __shared__ float As[8][128];                    // [k][m]

    const int tid = threadIdx.x;
    const int brow = blockIdx.x * 128;
    const int tr = tid >> 4;       // 0..15 -> rows tr*8..tr*8+7
    const int tc = tid & 15;       // 0..15 -> cols tc*8..tc*8+7

    unsigned long long acc[4][8];
#pragma unroll
    for (int i = 0; i < 4; i++)
#pragma unroll
        for (int j = 0; j < 8; j++) acc[i][j] = 0ull;

    // A-load mapping: 128 rows x 8 k = 256 float4 (one per thread)
    const int a_row = tid >> 1;
    const int a_k   = (tid & 1) << 2;
    // B-load mapping: 8 k x 32 float4-cols
    const int b_k   = tid >> 5;             // 0..7
    const int b_n4  = tid & 31;             // 0..31
    const int b_sup = b_n4 >> 4;
    const int b_in  = (b_n4 & 15) << 2;

    const bool a_ok = (brow + a_row) < NN;
    const float* xp = X + (size_t)(brow + a_row) * ID + a_k;
    const float* wp = W + (size_t)b_sup * (ID * OD) + (size_t)b_k * OD + b_in;

    char* bs2base = reinterpret_cast<char*>(Bs2);

    for (int k0 = 0; k0 < ID; k0 += 8) {
        float4 av = make_float4(0.f, 0.f, 0.f, 0.f);
        if (a_ok) av = *reinterpret_cast<const float4*>(xp + k0);
        float4 bv = *reinterpret_cast<const float4*>(wp + (size_t)k0 * OD);

        As[a_k + 0][a_row] = av.x;
        As[a_k + 1][a_row] = av.y;
        As[a_k + 2][a_row] = av.z;
        As[a_k + 3][a_row] = av.w;

        // duplicated B with SW128 swizzle within each 1024B row
        {
            float bvals[4] = {bv.x, bv.y, bv.z, bv.w};
#pragma unroll
            for (int j = 0; j < 4; j++) {
                unsigned byte = (unsigned)(b_k * 1024 + (b_n4 * 4 + j) * 8);
                *reinterpret_cast<float2*>(bs2base + SWB(byte)) =
                    make_float2(bvals[j], bvals[j]);
            }
        }
        __syncthreads();

#pragma unroll
        for (int kk = 0; kk < 8; kk++) {
            unsigned long long a2[4];
#pragma unroll
            for (int ip = 0; ip < 4; ip++)
                a2[ip] = *reinterpret_cast<const unsigned long long*>(
                    &As[kk][tr * 8 + 2 * ip]);

            unsigned long long b2[8];
#pragma unroll
            for (int q = 0; q < 4; q++) {
                unsigned byte = (unsigned)(kk * 1024 + tc * 64 + q * 16);
                ulonglong2 v = *reinterpret_cast<const ulonglong2*>(bs2base + SWB(byte));
                b2[q * 2] = v.x;
                b2[q * 2 + 1] = v.y;
            }

#pragma unroll
            for (int ip = 0; ip < 4; ip++)
#pragma unroll
                for (int j = 0; j < 8; j++) FMA2(acc[ip][j], a2[ip], b2[j]);
        }
        __syncthreads();
    }

    // store fp16: cols tc*8..tc*8+7 lie in one support
    const int sup = tc >> 3;
    const int o = (tc * 8) & 63;
    __half* dbase = g_preh + (size_t)sup * NN * OD + o;
#pragma unroll
    for (int ip = 0; ip < 4; ip++) {
        float lo[8], hi[8];
#pragma unroll
        for (int j = 0; j < 8; j++) {
            float2 f = *reinterpret_cast<float2*>(&acc[ip][j]);
            lo[j] = f.x;
            hi[j] = f.y;
        }
        int m0 = brow + tr * 8 + 2 * ip;
#pragma unroll
        for (int c = 0; c < 2; c++) {
            int m = m0 + c;
            if (m < NN) {
                const float* f = c ? hi : lo;
                __half2 h[4];
#pragma unroll
                for (int q = 0; q < 4; q++)
                    h[q] = __floats2half2_rn(f[q * 2], f[q * 2 + 1]);
                uint4 pk;
                pk.x = *reinterpret_cast<unsigned*>(&h[0]);
                pk.y = *reinterpret_cast<unsigned*>(&h[1]);
                pk.z = *reinterpret_cast<unsigned*>(&h[2]);
                pk.w = *reinterpret_cast<unsigned*>(&h[3]);
                *reinterpret_cast<uint4*>(dbase + (size_t)m * OD) = pk;
            }
        }
    }
}

// SPMM scatter: 16 threads per (support, edge); each thread handles 4 of the 64
// outputs. Gather fp16 (8B/thread, one 128B line per edge row), convert, scale,
// vector RED into out.
__global__ void __launch_bounds__(256) spmm_kernel(const float* __restrict__ ev,
                                                   const int* __restrict__ es,
                                                   const int* __restrict__ ed,
                                                   float* __restrict__ out) {
    int idx = blockIdx.x * 256 + threadIdx.x;
    int e = idx >> 4;               // 0 .. 2*NE-1 ([2][NE] contiguous)
    if (e >= 2 * NE) return;
    int t = idx & 15;

    int src = __ldg(es + e);
    int dst = __ldg(ed + e);
    float val = __ldg(ev + e);
    int sup = (e >= NE) ? 1 : 0;

    const uint2* prow = reinterpret_cast<const uint2*>(
        g_preh + ((size_t)sup * NN + (size_t)src) * OD);
    uint2 hv = __ldg(prow + t);
    __half2 h01 = *reinterpret_cast<__half2*>(&hv.x);
    __half2 h23 = *reinterpret_cast<__half2*>(&hv.y);
    float2 f01 = __half22float2(h01);
    float2 f23 = __half22float2(h23);

    float* addr = out + (size_t)dst * OD + t * 4;
    asm volatile("red.global.add.v4.f32 [%0], {%1, %2, %3, %4};"
                 :: "l"(addr), "f"(f01.x * val), "f"(f01.y * val),
                    "f"(f23.x * val), "f"(f23.y * val)
                 : "memory");
}

__global__ void __launch_bounds__(256) relu_kernel(float4* __restrict__ out, int n4) {
    int i = blockIdx.x * 256 + threadIdx.x;
    if (i < n4) {
        float4 v = out[i];
        v.x = fmaxf(v.x, 0.f);
        v.y = fmaxf(v.y, 0.f);
        v.z = fmaxf(v.z, 0.f);
        v.w = fmaxf(v.w, 0.f);
        out[i] = v;
    }
}

extern "C" void kernel_launch(void* const* d_in, const int* in_sizes, int n_in,
                              void* d_out, int out_size) {
    const float* x  = (const float*)d_in[0];   // [NN, 256]
    const float* W  = (const float*)d_in[1];   // [2, 256, 64]
    const float* ev = (const float*)d_in[2];   // [2, NE]
    const int*   es = (const int*)d_in[3];     // [2, NE]
    const int*   ed = (const int*)d_in[4];     // [2, NE]
    float* out = (float*)d_out;                // [NN, 64]

    const int n4 = NN * OD / 4;

    cudaMemsetAsync(d_out, 0, (size_t)NN * OD * sizeof(float));
    gemm_f32x2_kernel<<<(NN + 127) / 128, 256>>>(x, W);

    const long long total = (long long)2 * NE * 16;
    spmm_kernel<<<(int)((total + 255) / 256), 256>>>(ev, es, ed, out);

    relu_kernel<<<(n4 + 255) / 256, 256>>>((float4*)out, n4);
}